// round 1
// baseline (speedup 1.0000x reference)
#include <cuda_runtime.h>
#include <math.h>

// Problem constants (fixed shapes for this dataset)
#define BATCH 2
#define SEQ   2048
#define DIM   2048
#define KVDIM 512
#define NH    16
#define NKV   4
#define HD    128

// Scratch (allocation-free rule: __device__ globals)
__device__ float g_Q[BATCH * SEQ * DIM];    // 33.5 MB
__device__ float g_K[BATCH * SEQ * KVDIM];  //  8.4 MB
__device__ float g_V[BATCH * SEQ * KVDIM];  //  8.4 MB
__device__ float g_AO[BATCH * SEQ * DIM];   // 33.5 MB

// ---------------------------------------------------------------------------
// GEMM: C[m][n] = sum_k A[m][k] * B[n][k]   (A: MxK row-major, B: NxK row-major)
// 64x64 block tile, 256 threads (16x16), 4x4 register tile, K-tile = 32.
// As/Bs stored transposed [k][m] with row stride 68 (16B-aligned, conflict-lite).
// ---------------------------------------------------------------------------
#define GKT 32
#define GPAD 68

__global__ __launch_bounds__(256) void gemm_nt(const float* __restrict__ A,
                                               const float* __restrict__ B,
                                               float* __restrict__ C,
                                               int M, int N, int K) {
    __shared__ float As[GKT][GPAD];
    __shared__ float Bs[GKT][GPAD];

    const int tid = threadIdx.x;
    const int tx = tid & 15;
    const int ty = tid >> 4;
    const int mBase = blockIdx.y * 64;
    const int nBase = blockIdx.x * 64;

    float acc[4][4];
#pragma unroll
    for (int i = 0; i < 4; i++)
#pragma unroll
        for (int j = 0; j < 4; j++) acc[i][j] = 0.f;

    for (int k0 = 0; k0 < K; k0 += GKT) {
#pragma unroll
        for (int i = 0; i < 8; i++) {
            int lin = tid + i * 256;           // 0..2047
            int m = lin >> 5;                  // 0..63
            int k = lin & 31;                  // 0..31
            As[k][m] = A[(size_t)(mBase + m) * K + k0 + k];
            Bs[k][m] = B[(size_t)(nBase + m) * K + k0 + k];
        }
        __syncthreads();
#pragma unroll
        for (int k = 0; k < GKT; k++) {
            float4 a = *(const float4*)&As[k][ty * 4];
            float4 b = *(const float4*)&Bs[k][tx * 4];
            float av[4] = {a.x, a.y, a.z, a.w};
            float bv[4] = {b.x, b.y, b.z, b.w};
#pragma unroll
            for (int i = 0; i < 4; i++)
#pragma unroll
                for (int j = 0; j < 4; j++) acc[i][j] += av[i] * bv[j];
        }
        __syncthreads();
    }

#pragma unroll
    for (int i = 0; i < 4; i++) {
        float* cp = C + (size_t)(mBase + ty * 4 + i) * N + nBase + tx * 4;
#pragma unroll
        for (int j = 0; j < 4; j++) cp[j] = acc[i][j];
    }
}

// ---------------------------------------------------------------------------
// RoPE in-place. X is [BATCH*SEQ, nCols]; heads of width HD at col h*HD.
// angle = l * 10000^(-2i/128) = l * exp(-i * ln(10000)/64)
// out[i]    = x[i]*cos - x[i+64]*sin
// out[i+64] = x[i+64]*cos + x[i]*sin
// ---------------------------------------------------------------------------
__global__ void rope_kernel(float* __restrict__ X, int nCols, int nHeads) {
    int idx = blockIdx.x * blockDim.x + threadIdx.x;   // total BATCH*SEQ*nHeads*64
    int i = idx & 63;
    int h = (idx >> 6) % nHeads;
    int row = idx / (64 * nHeads);                     // b*SEQ + l
    int l = row & (SEQ - 1);

    float freq = expf(-(float)i * 0.14391156831212787f);  // ln(10000)/64
    float ang = (float)l * freq;
    float s, c;
    sincosf(ang, &s, &c);

    float* p = X + (size_t)row * nCols + h * HD + i;
    float x1 = p[0];
    float x2 = p[64];
    p[0]  = x1 * c - x2 * s;
    p[64] = x2 * c + x1 * s;
}

// ---------------------------------------------------------------------------
// Flash attention (fp32, causal). Grid: (SEQ/64, NH, BATCH). 256 threads.
// Q tile 64 rows x 128 dims, KV tiles of 64. Online softmax.
// smem: Qs[128][68], Ks[128][68], Vs[64][132]; Ps aliases Ks.  103424 bytes.
// Thread (ty,tx) in 16x16: S-tile rows ty*4..+3, cols tx*4..+3;
//                          O-tile rows ty*4..+3, cols tx*8..+7.
// ---------------------------------------------------------------------------
#define APAD 68
#define VPAD 132
#define ATTN_SMEM_BYTES ((2 * HD * APAD + 64 * VPAD) * (int)sizeof(float))

__global__ __launch_bounds__(256, 2) void attn_kernel(const float* __restrict__ Q,
                                                      const float* __restrict__ K,
                                                      const float* __restrict__ V,
                                                      float* __restrict__ O) {
    extern __shared__ float sm[];
    float* Qs = sm;                    // [128][68]
    float* Ks = sm + HD * APAD;        // [128][68]
    float* Vs = sm + 2 * HD * APAD;    // [64][132]
    float* Ps = Ks;                    // alias: [64][68]

    const int tid = threadIdx.x;
    const int tx = tid & 15;
    const int ty = tid >> 4;
    const int qTile = blockIdx.x;
    const int h = blockIdx.y;
    const int b = blockIdx.z;
    const int kh = h / (NH / NKV);
    const int qBase = qTile * 64;
    const float scale = 0.08838834764831845f;  // 1/sqrt(128)

    // Load Q tile (transposed, pre-scaled)
    const float* Qp = Q + ((size_t)(b * SEQ + qBase)) * DIM + h * HD;
#pragma unroll
    for (int i = 0; i < 32; i++) {
        int lin = tid + i * 256;
        int r = lin >> 7;      // 0..63
        int d = lin & 127;     // 0..127
        Qs[d * APAD + r] = Qp[(size_t)r * DIM + d] * scale;
    }

    float m[4], l[4], o[4][8];
#pragma unroll
    for (int i = 0; i < 4; i++) {
        m[i] = -1e30f;
        l[i] = 0.f;
#pragma unroll
        for (int j = 0; j < 8; j++) o[i][j] = 0.f;
    }

    const int nT = qTile + 1;
    for (int t = 0; t < nT; t++) {
        const float* Kp = K + ((size_t)(b * SEQ + t * 64)) * KVDIM + kh * HD;
        const float* Vp = V + ((size_t)(b * SEQ + t * 64)) * KVDIM + kh * HD;
        __syncthreads();  // previous iteration done with Ks(=Ps)/Vs; Qs load done (t==0)
#pragma unroll
        for (int i = 0; i < 32; i++) {
            int lin = tid + i * 256;
            int r = lin >> 7;
            int d = lin & 127;
            Ks[d * APAD + r] = Kp[(size_t)r * KVDIM + d];
            Vs[r * VPAD + d] = Vp[(size_t)r * KVDIM + d];
        }
        __syncthreads();

        // S = Qs^T * Ks  (4x4 per thread)
        float s4[4][4];
#pragma unroll
        for (int i = 0; i < 4; i++)
#pragma unroll
            for (int j = 0; j < 4; j++) s4[i][j] = 0.f;

#pragma unroll 4
        for (int d = 0; d < HD; d++) {
            float4 a = *(const float4*)&Qs[d * APAD + ty * 4];
            float4 bb = *(const float4*)&Ks[d * APAD + tx * 4];
            float av[4] = {a.x, a.y, a.z, a.w};
            float bv[4] = {bb.x, bb.y, bb.z, bb.w};
#pragma unroll
            for (int i = 0; i < 4; i++)
#pragma unroll
                for (int j = 0; j < 4; j++) s4[i][j] += av[i] * bv[j];
        }

        // Causal mask on the diagonal tile
        if (t == qTile) {
#pragma unroll
            for (int i = 0; i < 4; i++) {
                int qi = ty * 4 + i;
#pragma unroll
                for (int j = 0; j < 4; j++) {
                    int ki = tx * 4 + j;
                    if (ki > qi) s4[i][j] = -1e30f;
                }
            }
        }

        // Online softmax update
#pragma unroll
        for (int i = 0; i < 4; i++) {
            float rm = fmaxf(fmaxf(s4[i][0], s4[i][1]), fmaxf(s4[i][2], s4[i][3]));
#pragma unroll
            for (int off = 8; off; off >>= 1)
                rm = fmaxf(rm, __shfl_xor_sync(0xffffffffu, rm, off));
            float mn = fmaxf(m[i], rm);
            float alpha = __expf(m[i] - mn);
            m[i] = mn;
            float rs = 0.f;
#pragma unroll
            for (int j = 0; j < 4; j++) {
                s4[i][j] = __expf(s4[i][j] - mn);
                rs += s4[i][j];
            }
#pragma unroll
            for (int off = 8; off; off >>= 1)
                rs += __shfl_xor_sync(0xffffffffu, rs, off);
            l[i] = l[i] * alpha + rs;
#pragma unroll
            for (int j = 0; j < 8; j++) o[i][j] *= alpha;
        }

        __syncthreads();  // all threads finished reading Ks before Ps overwrite
#pragma unroll
        for (int i = 0; i < 4; i++)
#pragma unroll
            for (int j = 0; j < 4; j++)
                Ps[(tx * 4 + j) * APAD + ty * 4 + i] = s4[i][j];
        __syncthreads();

        // O += P * V   (4x8 per thread)
#pragma unroll 2
        for (int c = 0; c < 64; c++) {
            float4 p4 = *(const float4*)&Ps[c * APAD + ty * 4];
            float4 v0 = *(const float4*)&Vs[c * VPAD + tx * 8];
            float4 v1 = *(const float4*)&Vs[c * VPAD + tx * 8 + 4];
            float pv[4] = {p4.x, p4.y, p4.z, p4.w};
            float vv[8] = {v0.x, v0.y, v0.z, v0.w, v1.x, v1.y, v1.z, v1.w};
#pragma unroll
            for (int i = 0; i < 4; i++)
#pragma unroll
                for (int j = 0; j < 8; j++) o[i][j] += pv[i] * vv[j];
        }
    }

    // Normalize + write (layout [b, q, h*HD+d] so Wo GEMM reads it directly)
    float* Op = O + ((size_t)(b * SEQ + qBase)) * DIM + h * HD;
#pragma unroll
    for (int i = 0; i < 4; i++) {
        float inv = 1.f / l[i];
#pragma unroll
        for (int j = 0; j < 8; j++)
            Op[(size_t)(ty * 4 + i) * DIM + tx * 8 + j] = o[i][j] * inv;
    }
}

// ---------------------------------------------------------------------------
// Launch
// ---------------------------------------------------------------------------
extern "C" void kernel_launch(void* const* d_in, const int* in_sizes, int n_in,
                              void* d_out, int out_size) {
    const float* x  = (const float*)d_in[0];
    const float* Wq = (const float*)d_in[1];
    const float* Wk = (const float*)d_in[2];
    const float* Wv = (const float*)d_in[3];
    const float* Wo = (const float*)d_in[4];
    float* out = (float*)d_out;

    float *Qb, *Kb, *Vb, *AOb;
    cudaGetSymbolAddress((void**)&Qb, g_Q);
    cudaGetSymbolAddress((void**)&Kb, g_K);
    cudaGetSymbolAddress((void**)&Vb, g_V);
    cudaGetSymbolAddress((void**)&AOb, g_AO);

    const int M = BATCH * SEQ;  // 4096

    // Projections: Q = x Wq^T, K = x Wk^T, V = x Wv^T
    gemm_nt<<<dim3(DIM / 64, M / 64), 256>>>(x, Wq, Qb, M, DIM, DIM);
    gemm_nt<<<dim3(KVDIM / 64, M / 64), 256>>>(x, Wk, Kb, M, KVDIM, DIM);
    gemm_nt<<<dim3(KVDIM / 64, M / 64), 256>>>(x, Wv, Vb, M, KVDIM, DIM);

    // RoPE on Q and K
    rope_kernel<<<(BATCH * SEQ * NH * 64) / 256, 256>>>(Qb, DIM, NH);
    rope_kernel<<<(BATCH * SEQ * NKV * 64) / 256, 256>>>(Kb, KVDIM, NKV);

    // Flash attention
    cudaFuncSetAttribute(attn_kernel, cudaFuncAttributeMaxDynamicSharedMemorySize,
                         ATTN_SMEM_BYTES);
    attn_kernel<<<dim3(SEQ / 64, NH, BATCH), 256, ATTN_SMEM_BYTES>>>(Qb, Kb, Vb, AOb);

    // Output projection
    gemm_nt<<<dim3(DIM / 64, M / 64), 256>>>(AOb, Wo, out, M, DIM, DIM);
}

// round 2
// speedup vs baseline: 2.6689x; 2.6689x over previous
#include <cuda_runtime.h>
#include <math.h>
#include <stdint.h>

#define BATCH 2
#define SEQ   2048
#define DIM   2048
#define KVDIM 512
#define NH    16
#define NKV   4
#define HD    128

// Scratch (__device__ globals: allocation-free rule)
__device__ float g_Q[BATCH * SEQ * DIM];
__device__ float g_K[BATCH * SEQ * KVDIM];
__device__ float g_V[BATCH * SEQ * KVDIM];
__device__ float g_AO[BATCH * SEQ * DIM];

__device__ __forceinline__ uint32_t f2tf(float x) {
    uint32_t y;
    asm("cvt.rna.tf32.f32 %0, %1;" : "=r"(y) : "f"(x));
    return y;
}

// D += A*B, m16n8k8 tf32, fp32 accum
__device__ __forceinline__ void mma8(float* d, const uint32_t* a, const uint32_t* b) {
    asm volatile(
        "mma.sync.aligned.m16n8k8.row.col.f32.tf32.tf32.f32 "
        "{%0,%1,%2,%3}, {%4,%5,%6,%7}, {%8,%9}, {%0,%1,%2,%3};"
        : "+f"(d[0]), "+f"(d[1]), "+f"(d[2]), "+f"(d[3])
        : "r"(a[0]), "r"(a[1]), "r"(a[2]), "r"(a[3]), "r"(b[0]), "r"(b[1]));
}

// ---------------------------------------------------------------------------
// GEMM: C[m][n] = sum_k A[m][k]*B[n][k]. Block 128x128, 8 warps (2Mx4N),
// warp tile 64x32, BK=16 double-buffered. smem stores tf32-rounded bits.
// ---------------------------------------------------------------------------
#define BM 128
#define BN 128
#define BK 16
#define GSTR 136  // 128 + 8 -> conflict-free frag loads (stride mod 32 == 8)

__global__ __launch_bounds__(256) void gemm_tf32(const float* __restrict__ A,
                                                 const float* __restrict__ B,
                                                 float* __restrict__ C,
                                                 int M, int N, int K) {
    __shared__ uint32_t As[2][BK][GSTR];
    __shared__ uint32_t Bs[2][BK][GSTR];

    const int tid = threadIdx.x;
    const int lane = tid & 31;
    const int warp = tid >> 5;
    const int wm = warp >> 2;   // 0..1
    const int wn = warp & 3;    // 0..3
    const int gr = lane >> 2, tc = lane & 3;
    const int mBase = blockIdx.y * BM, nBase = blockIdx.x * BN;

    const int row = tid >> 1;            // 0..127
    const int kc0 = (tid & 1) * 4;       // 0 or 4

    float acc[4][4][4];
#pragma unroll
    for (int i = 0; i < 4; i++)
#pragma unroll
        for (int j = 0; j < 4; j++)
#pragma unroll
            for (int r = 0; r < 4; r++) acc[i][j][r] = 0.f;

    const int nK = K / BK;

    // stage tile kt into buffer bsel
#define STAGE(kt, bsel)                                                        \
    do {                                                                       \
        const float* Ap = A + (size_t)(mBase + row) * K + (kt) * BK;           \
        const float* Bp = B + (size_t)(nBase + row) * K + (kt) * BK;           \
        _Pragma("unroll") for (int i = 0; i < 2; i++) {                        \
            int kc = kc0 + i * 8;                                              \
            float4 a4 = *(const float4*)(Ap + kc);                             \
            float4 b4 = *(const float4*)(Bp + kc);                             \
            As[bsel][kc + 0][row] = f2tf(a4.x);                                \
            As[bsel][kc + 1][row] = f2tf(a4.y);                                \
            As[bsel][kc + 2][row] = f2tf(a4.z);                                \
            As[bsel][kc + 3][row] = f2tf(a4.w);                                \
            Bs[bsel][kc + 0][row] = f2tf(b4.x);                                \
            Bs[bsel][kc + 1][row] = f2tf(b4.y);                                \
            Bs[bsel][kc + 2][row] = f2tf(b4.z);                                \
            Bs[bsel][kc + 3][row] = f2tf(b4.w);                                \
        }                                                                      \
    } while (0)

    STAGE(0, 0);
    __syncthreads();

    for (int kt = 0; kt < nK; kt++) {
        int buf = kt & 1;
        if (kt + 1 < nK) STAGE(kt + 1, buf ^ 1);

#pragma unroll
        for (int ks = 0; ks < 2; ks++) {
            int k0 = ks * 8;
            uint32_t af[4][4], bf[4][2];
#pragma unroll
            for (int mt = 0; mt < 4; mt++) {
                int m0 = wm * 64 + mt * 16;
                af[mt][0] = As[buf][k0 + tc][m0 + gr];
                af[mt][1] = As[buf][k0 + tc][m0 + gr + 8];
                af[mt][2] = As[buf][k0 + tc + 4][m0 + gr];
                af[mt][3] = As[buf][k0 + tc + 4][m0 + gr + 8];
            }
#pragma unroll
            for (int nt = 0; nt < 4; nt++) {
                int n0 = wn * 32 + nt * 8;
                bf[nt][0] = Bs[buf][k0 + tc][n0 + gr];
                bf[nt][1] = Bs[buf][k0 + tc + 4][n0 + gr];
            }
#pragma unroll
            for (int mt = 0; mt < 4; mt++)
#pragma unroll
                for (int nt = 0; nt < 4; nt++) mma8(acc[mt][nt], af[mt], bf[nt]);
        }
        __syncthreads();
    }

#pragma unroll
    for (int mt = 0; mt < 4; mt++) {
        int m0 = mBase + wm * 64 + mt * 16;
#pragma unroll
        for (int nt = 0; nt < 4; nt++) {
            int n0 = nBase + wn * 32 + nt * 8 + 2 * tc;
            float* cp = C + (size_t)(m0 + gr) * N + n0;
            cp[0] = acc[mt][nt][0];
            cp[1] = acc[mt][nt][1];
            float* cp2 = C + (size_t)(m0 + gr + 8) * N + n0;
            cp2[0] = acc[mt][nt][2];
            cp2[1] = acc[mt][nt][3];
        }
    }
#undef STAGE
}

// ---------------------------------------------------------------------------
// RoPE in-place (unchanged; 20us)
// ---------------------------------------------------------------------------
__global__ void rope_kernel(float* __restrict__ X, int nCols, int nHeads) {
    int idx = blockIdx.x * blockDim.x + threadIdx.x;
    int i = idx & 63;
    int h = (idx >> 6) % nHeads;
    int row = idx / (64 * nHeads);
    int l = row & (SEQ - 1);

    float freq = expf(-(float)i * 0.14391156831212787f);
    float ang = (float)l * freq;
    float s, c;
    sincosf(ang, &s, &c);

    float* p = X + (size_t)row * nCols + h * HD + i;
    float x1 = p[0];
    float x2 = p[64];
    p[0] = x1 * c - x2 * s;
    p[64] = x2 * c + x1 * s;
}

// ---------------------------------------------------------------------------
// Flash attention with tf32 mma. CTA: 256 thr (8 warps), 128 q-rows
// (16 per warp), K-tiles of 64. Q resident in smem; K staged transposed;
// P round-trips through smem (warp-private rows -> only __syncwarp needed).
// ---------------------------------------------------------------------------
#define QROWS 128
#define QSTR 132  // stride mod 32 == 4: (4q + d) distinct banks
#define KSTR 72   // stride mod 32 == 8
#define VSTR 136
#define PSTR 68
#define ATTN_SMEM ((QROWS * QSTR + HD * KSTR + 64 * VSTR + QROWS * PSTR) * 4)

__global__ __launch_bounds__(256) void attn_tc(const float* __restrict__ Q,
                                               const float* __restrict__ K,
                                               const float* __restrict__ V,
                                               float* __restrict__ O) {
    extern __shared__ uint32_t sm[];
    uint32_t* Qs = sm;                    // [128][QSTR]  q x d
    uint32_t* Ks = Qs + QROWS * QSTR;     // [128][KSTR]  d x key
    uint32_t* Vs = Ks + HD * KSTR;        // [64][VSTR]   key x d
    uint32_t* Ps = Vs + 64 * VSTR;        // [128][PSTR]  q x key

    const int tid = threadIdx.x, lane = tid & 31, warp = tid >> 5;
    const int gr = lane >> 2, tc = lane & 3;
    const int qTile = blockIdx.x, h = blockIdx.y, b = blockIdx.z;
    const int kh = h >> 2;  // NH/NKV = 4
    const int qBase = qTile * QROWS;
    const float scale = 0.08838834764831845f;

    // Stage Q (scaled, tf32)
    {
        const float* Qp = Q + ((size_t)(b * SEQ + qBase)) * DIM + h * HD;
#pragma unroll
        for (int i = 0; i < 16; i++) {
            int idx = tid + i * 256;   // 0..4095
            int q = idx >> 5;
            int d4 = idx & 31;
            float4 v = *(const float4*)(Qp + (size_t)q * DIM + 4 * d4);
            uint4 u;
            u.x = f2tf(v.x * scale);
            u.y = f2tf(v.y * scale);
            u.z = f2tf(v.z * scale);
            u.w = f2tf(v.w * scale);
            *(uint4*)&Qs[q * QSTR + 4 * d4] = u;
        }
    }

    float m0r = -1e30f, m1r = -1e30f, l0 = 0.f, l1 = 0.f;
    float o[16][4];
#pragma unroll
    for (int i = 0; i < 16; i++)
#pragma unroll
        for (int j = 0; j < 4; j++) o[i][j] = 0.f;

    const int q0 = warp * 16;
    const int nT = 2 * qTile + 2;

    for (int t = 0; t < nT; t++) {
        __syncthreads();  // prev iter done reading Ks/Vs (and Qs staged, t==0)
        // Stage K transposed: Ks[d][key]
        {
            const float* Kp = K + ((size_t)(b * SEQ + t * 64)) * KVDIM + kh * HD;
#pragma unroll
            for (int i = 0; i < 8; i++) {
                int key = lane + 32 * (i & 1);
                int d4 = warp + 8 * (i >> 1);
                float4 v = *(const float4*)(Kp + (size_t)key * KVDIM + 4 * d4);
                Ks[(4 * d4 + 0) * KSTR + key] = f2tf(v.x);
                Ks[(4 * d4 + 1) * KSTR + key] = f2tf(v.y);
                Ks[(4 * d4 + 2) * KSTR + key] = f2tf(v.z);
                Ks[(4 * d4 + 3) * KSTR + key] = f2tf(v.w);
            }
        }
        // Stage V: Vs[key][d]
        {
            const float* Vp = V + ((size_t)(b * SEQ + t * 64)) * KVDIM + kh * HD;
#pragma unroll
            for (int i = 0; i < 8; i++) {
                int idx = tid + i * 256;  // 0..2047
                int key = idx >> 5;
                int d4 = idx & 31;
                float4 v = *(const float4*)(Vp + (size_t)key * KVDIM + 4 * d4);
                uint4 u;
                u.x = f2tf(v.x);
                u.y = f2tf(v.y);
                u.z = f2tf(v.z);
                u.w = f2tf(v.w);
                *(uint4*)&Vs[key * VSTR + 4 * d4] = u;
            }
        }
        __syncthreads();

        // S = Q * K^T (16 q-rows x 64 keys per warp)
        float s[8][4];
#pragma unroll
        for (int nt = 0; nt < 8; nt++)
#pragma unroll
            for (int r = 0; r < 4; r++) s[nt][r] = 0.f;

#pragma unroll
        for (int dk = 0; dk < 16; dk++) {
            int d0 = dk * 8;
            uint32_t aq[4];
            aq[0] = Qs[(q0 + gr) * QSTR + d0 + tc];
            aq[1] = Qs[(q0 + gr + 8) * QSTR + d0 + tc];
            aq[2] = Qs[(q0 + gr) * QSTR + d0 + tc + 4];
            aq[3] = Qs[(q0 + gr + 8) * QSTR + d0 + tc + 4];
#pragma unroll
            for (int nt = 0; nt < 8; nt++) {
                uint32_t bk[2];
                bk[0] = Ks[(d0 + tc) * KSTR + nt * 8 + gr];
                bk[1] = Ks[(d0 + tc + 4) * KSTR + nt * 8 + gr];
                mma8(s[nt], aq, bk);
            }
        }

        // Causal mask (only last two tiles can cross the diagonal)
        if (t * 64 >= qBase) {
            int qrow = qBase + q0 + gr;
            int kcol = t * 64 + 2 * tc;
#pragma unroll
            for (int nt = 0; nt < 8; nt++) {
                int kc = kcol + nt * 8;
                if (kc > qrow) s[nt][0] = -1e30f;
                if (kc + 1 > qrow) s[nt][1] = -1e30f;
                if (kc > qrow + 8) s[nt][2] = -1e30f;
                if (kc + 1 > qrow + 8) s[nt][3] = -1e30f;
            }
        }

        // Online softmax (rows gr and gr+8; quad = 4 lanes share a row)
        float rm0 = -1e30f, rm1 = -1e30f;
#pragma unroll
        for (int nt = 0; nt < 8; nt++) {
            rm0 = fmaxf(rm0, fmaxf(s[nt][0], s[nt][1]));
            rm1 = fmaxf(rm1, fmaxf(s[nt][2], s[nt][3]));
        }
        rm0 = fmaxf(rm0, __shfl_xor_sync(0xffffffffu, rm0, 1));
        rm0 = fmaxf(rm0, __shfl_xor_sync(0xffffffffu, rm0, 2));
        rm1 = fmaxf(rm1, __shfl_xor_sync(0xffffffffu, rm1, 1));
        rm1 = fmaxf(rm1, __shfl_xor_sync(0xffffffffu, rm1, 2));

        float mn0 = fmaxf(m0r, rm0), mn1 = fmaxf(m1r, rm1);
        float a0 = __expf(m0r - mn0), a1 = __expf(m1r - mn1);
        m0r = mn0;
        m1r = mn1;

        float rs0 = 0.f, rs1 = 0.f;
#pragma unroll
        for (int nt = 0; nt < 8; nt++) {
            s[nt][0] = __expf(s[nt][0] - mn0);
            s[nt][1] = __expf(s[nt][1] - mn0);
            s[nt][2] = __expf(s[nt][2] - mn1);
            s[nt][3] = __expf(s[nt][3] - mn1);
            rs0 += s[nt][0] + s[nt][1];
            rs1 += s[nt][2] + s[nt][3];
        }
        rs0 += __shfl_xor_sync(0xffffffffu, rs0, 1);
        rs0 += __shfl_xor_sync(0xffffffffu, rs0, 2);
        rs1 += __shfl_xor_sync(0xffffffffu, rs1, 1);
        rs1 += __shfl_xor_sync(0xffffffffu, rs1, 2);
        l0 = l0 * a0 + rs0;
        l1 = l1 * a1 + rs1;

#pragma unroll
        for (int ot = 0; ot < 16; ot++) {
            o[ot][0] *= a0;
            o[ot][1] *= a0;
            o[ot][2] *= a1;
            o[ot][3] *= a1;
        }

        // P -> smem (warp-private rows), then PV mma
#pragma unroll
        for (int nt = 0; nt < 8; nt++) {
            int c = nt * 8 + 2 * tc;
            Ps[(q0 + gr) * PSTR + c] = f2tf(s[nt][0]);
            Ps[(q0 + gr) * PSTR + c + 1] = f2tf(s[nt][1]);
            Ps[(q0 + gr + 8) * PSTR + c] = f2tf(s[nt][2]);
            Ps[(q0 + gr + 8) * PSTR + c + 1] = f2tf(s[nt][3]);
        }
        __syncwarp();

#pragma unroll
        for (int kk = 0; kk < 8; kk++) {
            uint32_t ap[4];
            ap[0] = Ps[(q0 + gr) * PSTR + kk * 8 + tc];
            ap[1] = Ps[(q0 + gr + 8) * PSTR + kk * 8 + tc];
            ap[2] = Ps[(q0 + gr) * PSTR + kk * 8 + tc + 4];
            ap[3] = Ps[(q0 + gr + 8) * PSTR + kk * 8 + tc + 4];
#pragma unroll
            for (int ot = 0; ot < 16; ot++) {
                uint32_t bv[2];
                bv[0] = Vs[(kk * 8 + tc) * VSTR + ot * 8 + gr];
                bv[1] = Vs[(kk * 8 + tc + 4) * VSTR + ot * 8 + gr];
                mma8(o[ot], ap, bv);
            }
        }
        __syncwarp();
    }

    // Normalize + write [b, q, h*HD + d]
    float inv0 = 1.f / l0, inv1 = 1.f / l1;
    float* Op = O + ((size_t)(b * SEQ + qBase + q0)) * DIM + h * HD;
#pragma unroll
    for (int ot = 0; ot < 16; ot++) {
        int d0 = ot * 8 + 2 * tc;
        Op[(size_t)gr * DIM + d0] = o[ot][0] * inv0;
        Op[(size_t)gr * DIM + d0 + 1] = o[ot][1] * inv0;
        Op[(size_t)(gr + 8) * DIM + d0] = o[ot][2] * inv1;
        Op[(size_t)(gr + 8) * DIM + d0 + 1] = o[ot][3] * inv1;
    }
}

// ---------------------------------------------------------------------------
extern "C" void kernel_launch(void* const* d_in, const int* in_sizes, int n_in,
                              void* d_out, int out_size) {
    const float* x = (const float*)d_in[0];
    const float* Wq = (const float*)d_in[1];
    const float* Wk = (const float*)d_in[2];
    const float* Wv = (const float*)d_in[3];
    const float* Wo = (const float*)d_in[4];
    float* out = (float*)d_out;

    float *Qb, *Kb, *Vb, *AOb;
    cudaGetSymbolAddress((void**)&Qb, g_Q);
    cudaGetSymbolAddress((void**)&Kb, g_K);
    cudaGetSymbolAddress((void**)&Vb, g_V);
    cudaGetSymbolAddress((void**)&AOb, g_AO);

    const int M = BATCH * SEQ;  // 4096

    gemm_tf32<<<dim3(DIM / BN, M / BM), 256>>>(x, Wq, Qb, M, DIM, DIM);
    gemm_tf32<<<dim3(KVDIM / BN, M / BM), 256>>>(x, Wk, Kb, M, KVDIM, DIM);
    gemm_tf32<<<dim3(KVDIM / BN, M / BM), 256>>>(x, Wv, Vb, M, KVDIM, DIM);

    rope_kernel<<<(BATCH * SEQ * NH * 64) / 256, 256>>>(Qb, DIM, NH);
    rope_kernel<<<(BATCH * SEQ * NKV * 64) / 256, 256>>>(Kb, KVDIM, NKV);

    cudaFuncSetAttribute(attn_tc, cudaFuncAttributeMaxDynamicSharedMemorySize,
                         ATTN_SMEM);
    attn_tc<<<dim3(SEQ / QROWS, NH, BATCH), 256, ATTN_SMEM>>>(Qb, Kb, Vb, AOb);

    gemm_tf32<<<dim3(DIM / BN, M / BM), 256>>>(AOb, Wo, out, M, DIM, DIM);
}

// round 3
// speedup vs baseline: 3.4191x; 1.2811x over previous
#include <cuda_runtime.h>
#include <math.h>
#include <stdint.h>

#define BATCH 2
#define SEQ   2048
#define DIM   2048
#define KVDIM 512
#define NH    16
#define NKV   4
#define HD    128

// Scratch (__device__ globals: allocation-free rule)
__device__ float g_Q[BATCH * SEQ * DIM];
__device__ float g_K[BATCH * SEQ * KVDIM];
__device__ float g_V[BATCH * SEQ * KVDIM];
__device__ float g_AO[BATCH * SEQ * DIM];
__device__ float g_X[BATCH * SEQ * DIM];
__device__ float g_Wq[DIM * DIM];
__device__ float g_Wk[KVDIM * DIM];
__device__ float g_Wv[KVDIM * DIM];
__device__ float g_Wo[DIM * DIM];

__device__ __forceinline__ uint32_t f2tf(float x) {
    uint32_t y;
    asm("cvt.rna.tf32.f32 %0, %1;" : "=r"(y) : "f"(x));
    return y;
}

__device__ __forceinline__ void mma8(float* d, const uint32_t* a, const uint32_t* b) {
    asm volatile(
        "mma.sync.aligned.m16n8k8.row.col.f32.tf32.tf32.f32 "
        "{%0,%1,%2,%3}, {%4,%5,%6,%7}, {%8,%9}, {%0,%1,%2,%3};"
        : "+f"(d[0]), "+f"(d[1]), "+f"(d[2]), "+f"(d[3])
        : "r"(a[0]), "r"(a[1]), "r"(a[2]), "r"(a[3]), "r"(b[0]), "r"(b[1]));
}

__device__ __forceinline__ void cp16(void* smem_dst, const void* gmem_src) {
    uint32_t sa = (uint32_t)__cvta_generic_to_shared(smem_dst);
    asm volatile("cp.async.cg.shared.global [%0], [%1], 16;\n" ::"r"(sa), "l"(gmem_src));
}
#define CP_COMMIT() asm volatile("cp.async.commit_group;\n" ::)
#define CP_WAIT(N) asm volatile("cp.async.wait_group %0;\n" ::"n"(N))

// ---------------------------------------------------------------------------
// Elementwise round-to-tf32 (bits kept in fp32 container)
// ---------------------------------------------------------------------------
__global__ void round_tf32(const float4* __restrict__ src, uint4* __restrict__ dst,
                           int n4) {
    int i = blockIdx.x * blockDim.x + threadIdx.x;
    if (i < n4) {
        float4 v = src[i];
        uint4 u;
        u.x = f2tf(v.x);
        u.y = f2tf(v.y);
        u.z = f2tf(v.z);
        u.w = f2tf(v.w);
        dst[i] = u;
    }
}

// ---------------------------------------------------------------------------
// GEMM: C[m][n] = sum_k A[m][k]*B[n][k]. Inputs are pre-rounded tf32 bits.
// Block 128x128, 8 warps (2Mx4N), warp 64x32, BK=16, 3-stage cp.async.
// smem rows [m][k] with stride 20 words (16B aligned, conflict-free frags).
// ---------------------------------------------------------------------------
#define BM 128
#define BN 128
#define BK 16
#define ASTR 20
#define GSTAGES 3
#define GEMM_SMEM (GSTAGES * 2 * 128 * ASTR * 4)

template <bool RND>
__global__ __launch_bounds__(256) void gemm_tf32(const float* __restrict__ Af,
                                                 const float* __restrict__ Bf,
                                                 float* __restrict__ C,
                                                 int M, int N, int K) {
    extern __shared__ uint32_t smp[];
    uint32_t* As = smp;                       // [3][128][20]
    uint32_t* Bs = smp + GSTAGES * 128 * ASTR;

    const uint32_t* A = (const uint32_t*)Af;
    const uint32_t* B = (const uint32_t*)Bf;

    const int tid = threadIdx.x;
    const int lane = tid & 31;
    const int warp = tid >> 5;
    const int wm = warp >> 2;
    const int wn = warp & 3;
    const int gr = lane >> 2, tc = lane & 3;
    const int mBase = blockIdx.y * BM, nBase = blockIdx.x * BN;

    const int srow = tid >> 2;        // 0..63 (x2 per matrix)
    const int scc = tid & 3;          // chunk in row

    float acc[4][4][4];
#pragma unroll
    for (int i = 0; i < 4; i++)
#pragma unroll
        for (int j = 0; j < 4; j++)
#pragma unroll
            for (int r = 0; r < 4; r++) acc[i][j][r] = 0.f;

    const int nK = K / BK;

#define GSTAGE(kt, s)                                                          \
    do {                                                                       \
        _Pragma("unroll") for (int i = 0; i < 2; i++) {                        \
            int row = srow + i * 64;                                           \
            const uint32_t* gA = A + (size_t)(mBase + row) * K + (kt) * BK + scc * 4; \
            const uint32_t* gB = B + (size_t)(nBase + row) * K + (kt) * BK + scc * 4; \
            cp16(&As[((s) * 128 + row) * ASTR + scc * 4], gA);                 \
            cp16(&Bs[((s) * 128 + row) * ASTR + scc * 4], gB);                 \
        }                                                                      \
    } while (0)

    GSTAGE(0, 0);
    CP_COMMIT();
    GSTAGE(1, 1);
    CP_COMMIT();

    for (int kt = 0; kt < nK; kt++) {
        CP_WAIT(1);
        __syncthreads();
        int nxt = kt + 2;
        if (nxt < nK) {
            int s = nxt % GSTAGES;
            GSTAGE(nxt, s);
        }
        CP_COMMIT();

        const uint32_t* Ab = As + (kt % GSTAGES) * 128 * ASTR;
        const uint32_t* Bb = Bs + (kt % GSTAGES) * 128 * ASTR;
#pragma unroll
        for (int ks = 0; ks < 2; ks++) {
            int k0 = ks * 8;
            uint32_t af[4][4], bf[4][2];
#pragma unroll
            for (int mt = 0; mt < 4; mt++) {
                int m0 = wm * 64 + mt * 16;
                af[mt][0] = Ab[(m0 + gr) * ASTR + k0 + tc];
                af[mt][1] = Ab[(m0 + gr + 8) * ASTR + k0 + tc];
                af[mt][2] = Ab[(m0 + gr) * ASTR + k0 + tc + 4];
                af[mt][3] = Ab[(m0 + gr + 8) * ASTR + k0 + tc + 4];
            }
#pragma unroll
            for (int nt = 0; nt < 4; nt++) {
                int n0 = wn * 32 + nt * 8;
                bf[nt][0] = Bb[(n0 + gr) * ASTR + k0 + tc];
                bf[nt][1] = Bb[(n0 + gr) * ASTR + k0 + tc + 4];
            }
#pragma unroll
            for (int mt = 0; mt < 4; mt++)
#pragma unroll
                for (int nt = 0; nt < 4; nt++) mma8(acc[mt][nt], af[mt], bf[nt]);
        }
        __syncthreads();
    }

#pragma unroll
    for (int mt = 0; mt < 4; mt++) {
        int m0 = mBase + wm * 64 + mt * 16;
#pragma unroll
        for (int nt = 0; nt < 4; nt++) {
            int n0 = nBase + wn * 32 + nt * 8 + 2 * tc;
            float* cp = C + (size_t)(m0 + gr) * N + n0;
            float* cp2 = C + (size_t)(m0 + gr + 8) * N + n0;
            if (RND) {
                ((uint32_t*)cp)[0] = f2tf(acc[mt][nt][0]);
                ((uint32_t*)cp)[1] = f2tf(acc[mt][nt][1]);
                ((uint32_t*)cp2)[0] = f2tf(acc[mt][nt][2]);
                ((uint32_t*)cp2)[1] = f2tf(acc[mt][nt][3]);
            } else {
                cp[0] = acc[mt][nt][0];
                cp[1] = acc[mt][nt][1];
                cp2[0] = acc[mt][nt][2];
                cp2[1] = acc[mt][nt][3];
            }
        }
    }
#undef GSTAGE
}

// ---------------------------------------------------------------------------
// RoPE in-place + scale + round to tf32 bits
// ---------------------------------------------------------------------------
__global__ void rope_kernel(float* __restrict__ X, int nCols, int nHeads,
                            float scale) {
    int idx = blockIdx.x * blockDim.x + threadIdx.x;
    int i = idx & 63;
    int h = (idx >> 6) % nHeads;
    int row = idx / (64 * nHeads);
    int l = row & (SEQ - 1);

    float freq = expf(-(float)i * 0.14391156831212787f);
    float ang = (float)l * freq;
    float s, c;
    sincosf(ang, &s, &c);

    float* p = X + (size_t)row * nCols + h * HD + i;
    float x1 = p[0];
    float x2 = p[64];
    ((uint32_t*)p)[0] = f2tf((x1 * c - x2 * s) * scale);
    ((uint32_t*)p)[64] = f2tf((x2 * c + x1 * s) * scale);
}

// ---------------------------------------------------------------------------
// Flash attention, tf32 mma, cp.async pipelined.
// CTA: 256 thr (8 warps x 16 q-rows = 128 q), KV tiles of 64.
// Qs[128][132], Ks[2][64][132], Vs[64][132], Ps[128][68]. 203776 B.
// ---------------------------------------------------------------------------
#define TSTR 132
#define PSTR 68
#define ATTN_SMEM ((128 * TSTR + 2 * 64 * TSTR + 64 * TSTR + 128 * PSTR) * 4)

__global__ __launch_bounds__(256) void attn_tc(const float* __restrict__ Qf,
                                               const float* __restrict__ Kf,
                                               const float* __restrict__ Vf,
                                               float* __restrict__ O) {
    extern __shared__ uint32_t sm[];
    uint32_t* Qs = sm;                     // [128][132]
    uint32_t* Ks = Qs + 128 * TSTR;        // [2][64][132]
    uint32_t* Vs = Ks + 2 * 64 * TSTR;     // [64][132]
    uint32_t* Ps = Vs + 64 * TSTR;         // [128][68]

    const uint32_t* Q = (const uint32_t*)Qf;
    const uint32_t* K = (const uint32_t*)Kf;
    const uint32_t* V = (const uint32_t*)Vf;

    const int tid = threadIdx.x, lane = tid & 31, warp = tid >> 5;
    const int gr = lane >> 2, tc = lane & 3;
    const int qTile = blockIdx.x, h = blockIdx.y, b = blockIdx.z;
    const int kh = h >> 2;
    const int qBase = qTile * 128;

    const uint32_t* Qp = Q + ((size_t)(b * SEQ + qBase)) * DIM + h * HD;
    const uint32_t* Kbase = K + ((size_t)(b * SEQ)) * KVDIM + kh * HD;
    const uint32_t* Vbase = V + ((size_t)(b * SEQ)) * KVDIM + kh * HD;

    // Prologue: stage Q (whole CTA tile) + K(0) in one cp.async group
    {
#pragma unroll
        for (int i = 0; i < 16; i++) {
            int c = tid + i * 256;     // 0..4095
            int q = c >> 5;
            int d4 = c & 31;
            cp16(&Qs[q * TSTR + d4 * 4], Qp + (size_t)q * DIM + d4 * 4);
        }
#pragma unroll
        for (int i = 0; i < 8; i++) {
            int c = tid + i * 256;     // 0..2047
            int key = c >> 5;
            int d4 = c & 31;
            cp16(&Ks[key * TSTR + d4 * 4], Kbase + (size_t)key * KVDIM + d4 * 4);
        }
        CP_COMMIT();
    }

    float m0r = -1e30f, m1r = -1e30f, l0 = 0.f, l1 = 0.f;
    float o[16][4];
#pragma unroll
    for (int i = 0; i < 16; i++)
#pragma unroll
        for (int j = 0; j < 4; j++) o[i][j] = 0.f;

    const int q0 = warp * 16;
    const int nT = 2 * qTile + 2;

    for (int t = 0; t < nT; t++) {
        const int buf = t & 1;
        CP_WAIT(0);          // K(t) (and Q on t==0) arrived
        __syncthreads();     // all warps done with previous iter (Vs, Ks[other])

        // Issue V(t)
        {
            const uint32_t* Vp = Vbase + (size_t)(t * 64) * KVDIM;
#pragma unroll
            for (int i = 0; i < 8; i++) {
                int c = tid + i * 256;
                int key = c >> 5;
                int d4 = c & 31;
                cp16(&Vs[key * TSTR + d4 * 4], Vp + (size_t)key * KVDIM + d4 * 4);
            }
        }
        CP_COMMIT();
        // Issue K(t+1)
        if (t + 1 < nT) {
            const uint32_t* Kp = Kbase + (size_t)((t + 1) * 64) * KVDIM;
            uint32_t* Kd = Ks + ((t + 1) & 1) * 64 * TSTR;
#pragma unroll
            for (int i = 0; i < 8; i++) {
                int c = tid + i * 256;
                int key = c >> 5;
                int d4 = c & 31;
                cp16(&Kd[key * TSTR + d4 * 4], Kp + (size_t)key * KVDIM + d4 * 4);
            }
        }
        CP_COMMIT();

        // S = Q * K^T  (16 q-rows x 64 keys per warp)
        const uint32_t* Kb = Ks + buf * 64 * TSTR;
        float s[8][4];
#pragma unroll
        for (int nt = 0; nt < 8; nt++)
#pragma unroll
            for (int r = 0; r < 4; r++) s[nt][r] = 0.f;

#pragma unroll
        for (int dk = 0; dk < 16; dk++) {
            int d0 = dk * 8;
            uint32_t aq[4];
            aq[0] = Qs[(q0 + gr) * TSTR + d0 + tc];
            aq[1] = Qs[(q0 + gr + 8) * TSTR + d0 + tc];
            aq[2] = Qs[(q0 + gr) * TSTR + d0 + tc + 4];
            aq[3] = Qs[(q0 + gr + 8) * TSTR + d0 + tc + 4];
#pragma unroll
            for (int nt = 0; nt < 8; nt++) {
                uint32_t bk[2];
                bk[0] = Kb[(nt * 8 + gr) * TSTR + d0 + tc];
                bk[1] = Kb[(nt * 8 + gr) * TSTR + d0 + tc + 4];
                mma8(s[nt], aq, bk);
            }
        }

        // Causal mask
        if (t * 64 >= qBase) {
            int qrow = qBase + q0 + gr;
            int kcol = t * 64 + 2 * tc;
#pragma unroll
            for (int nt = 0; nt < 8; nt++) {
                int kc = kcol + nt * 8;
                if (kc > qrow) s[nt][0] = -1e30f;
                if (kc + 1 > qrow) s[nt][1] = -1e30f;
                if (kc > qrow + 8) s[nt][2] = -1e30f;
                if (kc + 1 > qrow + 8) s[nt][3] = -1e30f;
            }
        }

        // Online softmax
        float rm0 = -1e30f, rm1 = -1e30f;
#pragma unroll
        for (int nt = 0; nt < 8; nt++) {
            rm0 = fmaxf(rm0, fmaxf(s[nt][0], s[nt][1]));
            rm1 = fmaxf(rm1, fmaxf(s[nt][2], s[nt][3]));
        }
        rm0 = fmaxf(rm0, __shfl_xor_sync(0xffffffffu, rm0, 1));
        rm0 = fmaxf(rm0, __shfl_xor_sync(0xffffffffu, rm0, 2));
        rm1 = fmaxf(rm1, __shfl_xor_sync(0xffffffffu, rm1, 1));
        rm1 = fmaxf(rm1, __shfl_xor_sync(0xffffffffu, rm1, 2));

        float mn0 = fmaxf(m0r, rm0), mn1 = fmaxf(m1r, rm1);
        float a0 = __expf(m0r - mn0), a1 = __expf(m1r - mn1);
        m0r = mn0;
        m1r = mn1;

        float rs0 = 0.f, rs1 = 0.f;
#pragma unroll
        for (int nt = 0; nt < 8; nt++) {
            s[nt][0] = __expf(s[nt][0] - mn0);
            s[nt][1] = __expf(s[nt][1] - mn0);
            s[nt][2] = __expf(s[nt][2] - mn1);
            s[nt][3] = __expf(s[nt][3] - mn1);
            rs0 += s[nt][0] + s[nt][1];
            rs1 += s[nt][2] + s[nt][3];
        }
        rs0 += __shfl_xor_sync(0xffffffffu, rs0, 1);
        rs0 += __shfl_xor_sync(0xffffffffu, rs0, 2);
        rs1 += __shfl_xor_sync(0xffffffffu, rs1, 1);
        rs1 += __shfl_xor_sync(0xffffffffu, rs1, 2);
        l0 = l0 * a0 + rs0;
        l1 = l1 * a1 + rs1;

#pragma unroll
        for (int ot = 0; ot < 16; ot++) {
            o[ot][0] *= a0;
            o[ot][1] *= a0;
            o[ot][2] *= a1;
            o[ot][3] *= a1;
        }

        // Wait V(t) (K(t+1) may still be in flight)
        CP_WAIT(1);
        __syncthreads();

        // P -> smem (warp-private rows)
#pragma unroll
        for (int nt = 0; nt < 8; nt++) {
            int c = nt * 8 + 2 * tc;
            Ps[(q0 + gr) * PSTR + c] = f2tf(s[nt][0]);
            Ps[(q0 + gr) * PSTR + c + 1] = f2tf(s[nt][1]);
            Ps[(q0 + gr + 8) * PSTR + c] = f2tf(s[nt][2]);
            Ps[(q0 + gr + 8) * PSTR + c + 1] = f2tf(s[nt][3]);
        }
        __syncwarp();

        // O += P * V
#pragma unroll
        for (int kk = 0; kk < 8; kk++) {
            uint32_t ap[4];
            ap[0] = Ps[(q0 + gr) * PSTR + kk * 8 + tc];
            ap[1] = Ps[(q0 + gr + 8) * PSTR + kk * 8 + tc];
            ap[2] = Ps[(q0 + gr) * PSTR + kk * 8 + tc + 4];
            ap[3] = Ps[(q0 + gr + 8) * PSTR + kk * 8 + tc + 4];
#pragma unroll
            for (int ot = 0; ot < 16; ot++) {
                uint32_t bv[2];
                bv[0] = Vs[(kk * 8 + tc) * TSTR + ot * 8 + gr];
                bv[1] = Vs[(kk * 8 + tc + 4) * TSTR + ot * 8 + gr];
                mma8(o[ot], ap, bv);
            }
        }
        __syncwarp();
    }

    // Normalize + write rounded tf32 bits (feeds the O-projection GEMM)
    float inv0 = 1.f / l0, inv1 = 1.f / l1;
    uint32_t* Op = (uint32_t*)(O + ((size_t)(b * SEQ + qBase + q0)) * DIM + h * HD);
#pragma unroll
    for (int ot = 0; ot < 16; ot++) {
        int d0 = ot * 8 + 2 * tc;
        Op[(size_t)gr * DIM + d0] = f2tf(o[ot][0] * inv0);
        Op[(size_t)gr * DIM + d0 + 1] = f2tf(o[ot][1] * inv0);
        Op[(size_t)(gr + 8) * DIM + d0] = f2tf(o[ot][2] * inv1);
        Op[(size_t)(gr + 8) * DIM + d0 + 1] = f2tf(o[ot][3] * inv1);
    }
}

// ---------------------------------------------------------------------------
extern "C" void kernel_launch(void* const* d_in, const int* in_sizes, int n_in,
                              void* d_out, int out_size) {
    const float* x = (const float*)d_in[0];
    const float* Wq = (const float*)d_in[1];
    const float* Wk = (const float*)d_in[2];
    const float* Wv = (const float*)d_in[3];
    const float* Wo = (const float*)d_in[4];
    float* out = (float*)d_out;

    float *Qb, *Kb, *Vb, *AOb, *Xb, *Wqb, *Wkb, *Wvb, *Wob;
    cudaGetSymbolAddress((void**)&Qb, g_Q);
    cudaGetSymbolAddress((void**)&Kb, g_K);
    cudaGetSymbolAddress((void**)&Vb, g_V);
    cudaGetSymbolAddress((void**)&AOb, g_AO);
    cudaGetSymbolAddress((void**)&Xb, g_X);
    cudaGetSymbolAddress((void**)&Wqb, g_Wq);
    cudaGetSymbolAddress((void**)&Wkb, g_Wk);
    cudaGetSymbolAddress((void**)&Wvb, g_Wv);
    cudaGetSymbolAddress((void**)&Wob, g_Wo);

    const int M = BATCH * SEQ;

    // Pre-round inputs to tf32 bits (rna)
    round_tf32<<<(M * DIM / 4 + 255) / 256, 256>>>((const float4*)x, (uint4*)Xb,
                                                   M * DIM / 4);
    round_tf32<<<(DIM * DIM / 4 + 255) / 256, 256>>>((const float4*)Wq, (uint4*)Wqb,
                                                     DIM * DIM / 4);
    round_tf32<<<(KVDIM * DIM / 4 + 255) / 256, 256>>>((const float4*)Wk, (uint4*)Wkb,
                                                       KVDIM * DIM / 4);
    round_tf32<<<(KVDIM * DIM / 4 + 255) / 256, 256>>>((const float4*)Wv, (uint4*)Wvb,
                                                       KVDIM * DIM / 4);
    round_tf32<<<(DIM * DIM / 4 + 255) / 256, 256>>>((const float4*)Wo, (uint4*)Wob,
                                                     DIM * DIM / 4);

    cudaFuncSetAttribute(gemm_tf32<false>, cudaFuncAttributeMaxDynamicSharedMemorySize,
                         GEMM_SMEM);
    cudaFuncSetAttribute(gemm_tf32<true>, cudaFuncAttributeMaxDynamicSharedMemorySize,
                         GEMM_SMEM);

    gemm_tf32<false><<<dim3(DIM / BN, M / BM), 256, GEMM_SMEM>>>(Xb, Wqb, Qb, M, DIM, DIM);
    gemm_tf32<false><<<dim3(KVDIM / BN, M / BM), 256, GEMM_SMEM>>>(Xb, Wkb, Kb, M, KVDIM, DIM);
    gemm_tf32<true><<<dim3(KVDIM / BN, M / BM), 256, GEMM_SMEM>>>(Xb, Wvb, Vb, M, KVDIM, DIM);

    const float scale = 0.08838834764831845f;  // 1/sqrt(128)
    rope_kernel<<<(BATCH * SEQ * NH * 64) / 256, 256>>>(Qb, DIM, NH, scale);
    rope_kernel<<<(BATCH * SEQ * NKV * 64) / 256, 256>>>(Kb, KVDIM, NKV, 1.0f);

    cudaFuncSetAttribute(attn_tc, cudaFuncAttributeMaxDynamicSharedMemorySize,
                         ATTN_SMEM);
    attn_tc<<<dim3(SEQ / 128, NH, BATCH), 256, ATTN_SMEM>>>(Qb, Kb, Vb, AOb);

    gemm_tf32<false><<<dim3(DIM / BN, M / BM), 256, GEMM_SMEM>>>(AOb, Wob, out, M, DIM, DIM);
}

// round 6
// speedup vs baseline: 6.2914x; 1.8401x over previous
#include <cuda_runtime.h>
#include <cuda_fp16.h>
#include <math.h>
#include <stdint.h>

#define BATCH 2
#define SEQ   2048
#define DIM   2048
#define KVDIM 512
#define NH    16
#define NKV   4
#define HD    128

// Scratch (__device__ globals: allocation-free rule)
__device__ __half g_Xh[BATCH * SEQ * DIM];
__device__ __half g_Wqh[DIM * DIM];
__device__ __half g_Wkh[KVDIM * DIM];
__device__ __half g_Wvh[KVDIM * DIM];
__device__ __half g_Woh[DIM * DIM];
__device__ __half g_Qh[BATCH * SEQ * DIM];
__device__ __half g_Kh[BATCH * SEQ * KVDIM];
__device__ __half g_Vh[BATCH * SEQ * KVDIM];
__device__ __half g_AOh[BATCH * SEQ * DIM];

__device__ __forceinline__ uint32_t h2u(__half2 h) {
    uint32_t u;
    memcpy(&u, &h, 4);
    return u;
}

__device__ __forceinline__ void mma16(float* d, const uint32_t* a, const uint32_t* b) {
    asm volatile(
        "mma.sync.aligned.m16n8k16.row.col.f32.f16.f16.f32 "
        "{%0,%1,%2,%3}, {%4,%5,%6,%7}, {%8,%9}, {%0,%1,%2,%3};"
        : "+f"(d[0]), "+f"(d[1]), "+f"(d[2]), "+f"(d[3])
        : "r"(a[0]), "r"(a[1]), "r"(a[2]), "r"(a[3]), "r"(b[0]), "r"(b[1]));
}

__device__ __forceinline__ void cp16(void* smem_dst, const void* gmem_src) {
    uint32_t sa = (uint32_t)__cvta_generic_to_shared(smem_dst);
    asm volatile("cp.async.cg.shared.global [%0], [%1], 16;\n" ::"r"(sa), "l"(gmem_src));
}
#define CP_COMMIT() asm volatile("cp.async.commit_group;\n" ::)
#define CP_WAIT(N) asm volatile("cp.async.wait_group %0;\n" ::"n"(N))

// ---------------------------------------------------------------------------
// fp32 -> fp16 conversion
// ---------------------------------------------------------------------------
__global__ void to_half(const float2* __restrict__ src, __half2* __restrict__ dst,
                        int n2) {
    int i = blockIdx.x * blockDim.x + threadIdx.x;
    if (i < n2) {
        float2 v = src[i];
        dst[i] = __floats2half2_rn(v.x, v.y);
    }
}

// ---------------------------------------------------------------------------
// fp16 GEMM: C[m][n] = sum_k A[m][k]*B[n][k].  Block 128x128, 8 warps (2Mx4N),
// warp 64x32, BK=32 halves, 3-stage cp.async. smem rows: 32 halves + pad
// (b32 stride 20 -> conflict-free quad-pattern frag loads).
// ---------------------------------------------------------------------------
#define HSTR2 20
#define HSTAGES 3
#define HSTAGE_U32 (128 * HSTR2)                     // per matrix per stage
#define HGEMM_SMEM (HSTAGES * 2 * HSTAGE_U32 * 4)    // 61440 B

template <bool HALF_OUT>
__global__ __launch_bounds__(256) void gemm_h(const __half* __restrict__ A,
                                              const __half* __restrict__ B,
                                              void* __restrict__ Cv,
                                              int M, int N, int K) {
    extern __shared__ uint32_t smp[];
    uint32_t* As = smp;
    uint32_t* Bs = smp + HSTAGES * HSTAGE_U32;

    const int tid = threadIdx.x;
    const int lane = tid & 31;
    const int warp = tid >> 5;
    const int wm = warp >> 2;
    const int wn = warp & 3;
    const int gr = lane >> 2, tc = lane & 3;
    const int mBase = blockIdx.y * 128, nBase = blockIdx.x * 128;

    float acc[4][4][4];
#pragma unroll
    for (int i = 0; i < 4; i++)
#pragma unroll
        for (int j = 0; j < 4; j++)
#pragma unroll
            for (int r = 0; r < 4; r++) acc[i][j][r] = 0.f;

    const int nK = K / 32;

    // stage k-tile kt into ring slot s (each thread: 4 cp16 = 2 per matrix)
#define GSTAGE(kt, s)                                                          \
    do {                                                                       \
        _Pragma("unroll") for (int i = 0; i < 2; i++) {                        \
            int c = tid + i * 256;            /* 0..511 */                     \
            int r = c >> 2, ch = c & 3;                                        \
            cp16(&As[((s)*128 + r) * HSTR2 + ch * 4],                          \
                 A + (size_t)(mBase + r) * K + (kt)*32 + ch * 8);              \
            cp16(&Bs[((s)*128 + r) * HSTR2 + ch * 4],                          \
                 B + (size_t)(nBase + r) * K + (kt)*32 + ch * 8);              \
        }                                                                      \
    } while (0)

    GSTAGE(0, 0);
    CP_COMMIT();
    GSTAGE(1, 1);
    CP_COMMIT();

    for (int kt = 0; kt < nK; kt++) {
        CP_WAIT(1);
        __syncthreads();
        int nxt = kt + 2;
        if (nxt < nK) GSTAGE(nxt, nxt % HSTAGES);
        CP_COMMIT();

        const uint32_t* Ab = As + (kt % HSTAGES) * HSTAGE_U32;
        const uint32_t* Bb = Bs + (kt % HSTAGES) * HSTAGE_U32;
#pragma unroll
        for (int ks = 0; ks < 2; ks++) {
            int k0 = ks * 8;  // b32 offset (16 halves)
            uint32_t af[4][4], bf[4][2];
#pragma unroll
            for (int mt = 0; mt < 4; mt++) {
                int m0 = wm * 64 + mt * 16;
                af[mt][0] = Ab[(m0 + gr) * HSTR2 + k0 + tc];
                af[mt][1] = Ab[(m0 + gr + 8) * HSTR2 + k0 + tc];
                af[mt][2] = Ab[(m0 + gr) * HSTR2 + k0 + tc + 4];
                af[mt][3] = Ab[(m0 + gr + 8) * HSTR2 + k0 + tc + 4];
            }
#pragma unroll
            for (int nt = 0; nt < 4; nt++) {
                int n0 = wn * 32 + nt * 8;
                bf[nt][0] = Bb[(n0 + gr) * HSTR2 + k0 + tc];
                bf[nt][1] = Bb[(n0 + gr) * HSTR2 + k0 + tc + 4];
            }
#pragma unroll
            for (int mt = 0; mt < 4; mt++)
#pragma unroll
                for (int nt = 0; nt < 4; nt++) mma16(acc[mt][nt], af[mt], bf[nt]);
        }
        __syncthreads();
    }
#undef GSTAGE

#pragma unroll
    for (int mt = 0; mt < 4; mt++) {
        int m0 = mBase + wm * 64 + mt * 16;
#pragma unroll
        for (int nt = 0; nt < 4; nt++) {
            int n0 = nBase + wn * 32 + nt * 8 + 2 * tc;
            if (HALF_OUT) {
                __half2* cp = (__half2*)((__half*)Cv + (size_t)(m0 + gr) * N + n0);
                __half2* cp2 = (__half2*)((__half*)Cv + (size_t)(m0 + gr + 8) * N + n0);
                *cp = __floats2half2_rn(acc[mt][nt][0], acc[mt][nt][1]);
                *cp2 = __floats2half2_rn(acc[mt][nt][2], acc[mt][nt][3]);
            } else {
                float* cp = (float*)Cv + (size_t)(m0 + gr) * N + n0;
                float* cp2 = (float*)Cv + (size_t)(m0 + gr + 8) * N + n0;
                cp[0] = acc[mt][nt][0];
                cp[1] = acc[mt][nt][1];
                cp2[0] = acc[mt][nt][2];
                cp2[1] = acc[mt][nt][3];
            }
        }
    }
}

// ---------------------------------------------------------------------------
// RoPE in-place on half data (+ optional scale folded in)
// ---------------------------------------------------------------------------
__global__ void rope_half(__half* __restrict__ X, int nCols, int nHeads,
                          float scale) {
    int idx = blockIdx.x * blockDim.x + threadIdx.x;
    int i = idx & 63;
    int h = (idx >> 6) % nHeads;
    int row = idx / (64 * nHeads);
    int l = row & (SEQ - 1);

    float freq = expf(-(float)i * 0.14391156831212787f);
    float ang = (float)l * freq;
    float s, c;
    sincosf(ang, &s, &c);

    __half* p = X + (size_t)row * nCols + h * HD + i;
    float x1 = __half2float(p[0]);
    float x2 = __half2float(p[64]);
    p[0] = __float2half_rn((x1 * c - x2 * s) * scale);
    p[64] = __float2half_rn((x2 * c + x1 * s) * scale);
}

// ---------------------------------------------------------------------------
// Flash attention, fp16 mma (m16n8k16), cp.async pipelined.
// CTA: 256 thr (8 warps x 16 q-rows = 128 q), KV tiles of 64.
// smem (halves, b32 strides): Qs[128][68], Ks[2][64][68], Vs[64][68], Ps[128][36]
// ---------------------------------------------------------------------------
#define AQS2 68
#define APS2 36
#define ATTN_SMEM ((128 * AQS2 + 2 * 64 * AQS2 + 64 * AQS2 + 128 * APS2) * 4)

__global__ __launch_bounds__(256) void attn_h(const __half* __restrict__ Q,
                                              const __half* __restrict__ K,
                                              const __half* __restrict__ V,
                                              __half* __restrict__ O) {
    extern __shared__ uint32_t sm[];
    uint32_t* Qs = sm;                       // [128][68] b32
    uint32_t* Ks = Qs + 128 * AQS2;          // [2][64][68]
    uint32_t* Vs = Ks + 2 * 64 * AQS2;       // [64][68]
    uint32_t* Ps = Vs + 64 * AQS2;           // [128][36]

    const int tid = threadIdx.x, lane = tid & 31, warp = tid >> 5;
    const int gr = lane >> 2, tc = lane & 3;
    const int qTile = blockIdx.x, h = blockIdx.y, b = blockIdx.z;
    const int kh = h >> 2;
    const int qBase = qTile * 128;

    const __half* Qp = Q + ((size_t)(b * SEQ + qBase)) * DIM + h * HD;
    const __half* Kbase = K + ((size_t)(b * SEQ)) * KVDIM + kh * HD;
    const __half* Vbase = V + ((size_t)(b * SEQ)) * KVDIM + kh * HD;

    // Prologue: stage Q (128x128h = 2048 chunks) + K(0) (1024 chunks)
    {
#pragma unroll
        for (int i = 0; i < 8; i++) {
            int c = tid + i * 256;          // 0..2047
            int q = c >> 4;
            int ch = c & 15;
            cp16((char*)Qs + q * (AQS2 * 4) + ch * 16,
                 Qp + (size_t)q * DIM + ch * 8);
        }
#pragma unroll
        for (int i = 0; i < 4; i++) {
            int c = tid + i * 256;          // 0..1023
            int key = c >> 4;
            int ch = c & 15;
            cp16((char*)Ks + key * (AQS2 * 4) + ch * 16,
                 Kbase + (size_t)key * KVDIM + ch * 8);
        }
        CP_COMMIT();
    }

    float m0r = -1e30f, m1r = -1e30f, l0 = 0.f, l1 = 0.f;
    float o[16][4];
#pragma unroll
    for (int i = 0; i < 16; i++)
#pragma unroll
        for (int j = 0; j < 4; j++) o[i][j] = 0.f;

    const int q0 = warp * 16;
    const int nT = 2 * qTile + 2;

    for (int t = 0; t < nT; t++) {
        const int buf = t & 1;
        CP_WAIT(0);
        __syncthreads();

        // Issue V(t)
        {
            const __half* Vp = Vbase + (size_t)(t * 64) * KVDIM;
#pragma unroll
            for (int i = 0; i < 4; i++) {
                int c = tid + i * 256;
                int key = c >> 4;
                int ch = c & 15;
                cp16((char*)Vs + key * (AQS2 * 4) + ch * 16,
                     Vp + (size_t)key * KVDIM + ch * 8);
            }
        }
        CP_COMMIT();
        // Issue K(t+1)
        if (t + 1 < nT) {
            const __half* Kp = Kbase + (size_t)((t + 1) * 64) * KVDIM;
            uint32_t* Kd = Ks + ((t + 1) & 1) * 64 * AQS2;
#pragma unroll
            for (int i = 0; i < 4; i++) {
                int c = tid + i * 256;
                int key = c >> 4;
                int ch = c & 15;
                cp16((char*)Kd + key * (AQS2 * 4) + ch * 16,
                     Kp + (size_t)key * KVDIM + ch * 8);
            }
        }
        CP_COMMIT();

        // S = Q * K^T  (16 q-rows x 64 keys per warp); 8 dk-steps of k16
        const uint32_t* Kb = Ks + buf * 64 * AQS2;
        float s[8][4];
#pragma unroll
        for (int nt = 0; nt < 8; nt++)
#pragma unroll
            for (int r = 0; r < 4; r++) s[nt][r] = 0.f;

#pragma unroll
        for (int dk = 0; dk < 8; dk++) {
            int k0 = dk * 8;  // b32 offset
            uint32_t aq[4];
            aq[0] = Qs[(q0 + gr) * AQS2 + k0 + tc];
            aq[1] = Qs[(q0 + gr + 8) * AQS2 + k0 + tc];
            aq[2] = Qs[(q0 + gr) * AQS2 + k0 + tc + 4];
            aq[3] = Qs[(q0 + gr + 8) * AQS2 + k0 + tc + 4];
#pragma unroll
            for (int nt = 0; nt < 8; nt++) {
                uint32_t bk[2];
                bk[0] = Kb[(nt * 8 + gr) * AQS2 + k0 + tc];
                bk[1] = Kb[(nt * 8 + gr) * AQS2 + k0 + tc + 4];
                mma16(s[nt], aq, bk);
            }
        }

        // Causal mask
        if (t * 64 >= qBase) {
            int qrow = qBase + q0 + gr;
            int kcol = t * 64 + 2 * tc;
#pragma unroll
            for (int nt = 0; nt < 8; nt++) {
                int kc = kcol + nt * 8;
                if (kc > qrow) s[nt][0] = -1e30f;
                if (kc + 1 > qrow) s[nt][1] = -1e30f;
                if (kc > qrow + 8) s[nt][2] = -1e30f;
                if (kc + 1 > qrow + 8) s[nt][3] = -1e30f;
            }
        }

        // Online softmax
        float rm0 = -1e30f, rm1 = -1e30f;
#pragma unroll
        for (int nt = 0; nt < 8; nt++) {
            rm0 = fmaxf(rm0, fmaxf(s[nt][0], s[nt][1]));
            rm1 = fmaxf(rm1, fmaxf(s[nt][2], s[nt][3]));
        }
        rm0 = fmaxf(rm0, __shfl_xor_sync(0xffffffffu, rm0, 1));
        rm0 = fmaxf(rm0, __shfl_xor_sync(0xffffffffu, rm0, 2));
        rm1 = fmaxf(rm1, __shfl_xor_sync(0xffffffffu, rm1, 1));
        rm1 = fmaxf(rm1, __shfl_xor_sync(0xffffffffu, rm1, 2));

        float mn0 = fmaxf(m0r, rm0), mn1 = fmaxf(m1r, rm1);
        float a0 = __expf(m0r - mn0), a1 = __expf(m1r - mn1);
        m0r = mn0;
        m1r = mn1;

        float rs0 = 0.f, rs1 = 0.f;
#pragma unroll
        for (int nt = 0; nt < 8; nt++) {
            s[nt][0] = __expf(s[nt][0] - mn0);
            s[nt][1] = __expf(s[nt][1] - mn0);
            s[nt][2] = __expf(s[nt][2] - mn1);
            s[nt][3] = __expf(s[nt][3] - mn1);
            rs0 += s[nt][0] + s[nt][1];
            rs1 += s[nt][2] + s[nt][3];
        }
        rs0 += __shfl_xor_sync(0xffffffffu, rs0, 1);
        rs0 += __shfl_xor_sync(0xffffffffu, rs0, 2);
        rs1 += __shfl_xor_sync(0xffffffffu, rs1, 1);
        rs1 += __shfl_xor_sync(0xffffffffu, rs1, 2);
        l0 = l0 * a0 + rs0;
        l1 = l1 * a1 + rs1;

#pragma unroll
        for (int ot = 0; ot < 16; ot++) {
            o[ot][0] *= a0;
            o[ot][1] *= a0;
            o[ot][2] *= a1;
            o[ot][3] *= a1;
        }

        // V(t) must have landed (K(t+1) group still in flight)
        CP_WAIT(1);
        __syncthreads();

        // P -> smem (half2, warp-private rows)
#pragma unroll
        for (int nt = 0; nt < 8; nt++) {
            Ps[(q0 + gr) * APS2 + nt * 4 + tc] =
                h2u(__floats2half2_rn(s[nt][0], s[nt][1]));
            Ps[(q0 + gr + 8) * APS2 + nt * 4 + tc] =
                h2u(__floats2half2_rn(s[nt][2], s[nt][3]));
        }
        __syncwarp();

        // O += P * V : 4 k-steps of 16 keys, 16 d-tiles of 8
        const ushort* Vu = (const ushort*)Vs;
#pragma unroll
        for (int kk = 0; kk < 4; kk++) {
            uint32_t ap[4];
            ap[0] = Ps[(q0 + gr) * APS2 + kk * 8 + tc];
            ap[1] = Ps[(q0 + gr + 8) * APS2 + kk * 8 + tc];
            ap[2] = Ps[(q0 + gr) * APS2 + kk * 8 + tc + 4];
            ap[3] = Ps[(q0 + gr + 8) * APS2 + kk * 8 + tc + 4];
            const int r0 = kk * 16 + 2 * tc;
#pragma unroll
            for (int ot = 0; ot < 16; ot++) {
                int col = ot * 8 + gr;
                uint32_t bv[2];
                bv[0] = (uint32_t)Vu[r0 * (AQS2 * 2) + col] |
                        ((uint32_t)Vu[(r0 + 1) * (AQS2 * 2) + col] << 16);
                bv[1] = (uint32_t)Vu[(r0 + 8) * (AQS2 * 2) + col] |
                        ((uint32_t)Vu[(r0 + 9) * (AQS2 * 2) + col] << 16);
                mma16(o[ot], ap, bv);
            }
        }
        __syncwarp();
    }

    // Normalize + write half (feeds O-projection GEMM)
    float inv0 = 1.f / l0, inv1 = 1.f / l1;
    __half* Op = O + ((size_t)(b * SEQ + qBase + q0)) * DIM + h * HD;
#pragma unroll
    for (int ot = 0; ot < 16; ot++) {
        int d0 = ot * 8 + 2 * tc;
        *(__half2*)(Op + (size_t)gr * DIM + d0) =
            __floats2half2_rn(o[ot][0] * inv0, o[ot][1] * inv0);
        *(__half2*)(Op + (size_t)(gr + 8) * DIM + d0) =
            __floats2half2_rn(o[ot][2] * inv1, o[ot][3] * inv1);
    }
}

// ---------------------------------------------------------------------------
extern "C" void kernel_launch(void* const* d_in, const int* in_sizes, int n_in,
                              void* d_out, int out_size) {
    const float* x = (const float*)d_in[0];
    const float* Wq = (const float*)d_in[1];
    const float* Wk = (const float*)d_in[2];
    const float* Wv = (const float*)d_in[3];
    const float* Wo = (const float*)d_in[4];
    float* out = (float*)d_out;

    __half *Xh, *Wqh, *Wkh, *Wvh, *Woh, *Qh, *Kh, *Vh, *AOh;
    cudaGetSymbolAddress((void**)&Xh, g_Xh);
    cudaGetSymbolAddress((void**)&Wqh, g_Wqh);
    cudaGetSymbolAddress((void**)&Wkh, g_Wkh);
    cudaGetSymbolAddress((void**)&Wvh, g_Wvh);
    cudaGetSymbolAddress((void**)&Woh, g_Woh);
    cudaGetSymbolAddress((void**)&Qh, g_Qh);
    cudaGetSymbolAddress((void**)&Kh, g_Kh);
    cudaGetSymbolAddress((void**)&Vh, g_Vh);
    cudaGetSymbolAddress((void**)&AOh, g_AOh);

    const int M = BATCH * SEQ;  // 4096

    to_half<<<(M * DIM / 2 + 255) / 256, 256>>>((const float2*)x, (__half2*)Xh,
                                                M * DIM / 2);
    to_half<<<(DIM * DIM / 2 + 255) / 256, 256>>>((const float2*)Wq, (__half2*)Wqh,
                                                  DIM * DIM / 2);
    to_half<<<(KVDIM * DIM / 2 + 255) / 256, 256>>>((const float2*)Wk, (__half2*)Wkh,
                                                    KVDIM * DIM / 2);
    to_half<<<(KVDIM * DIM / 2 + 255) / 256, 256>>>((const float2*)Wv, (__half2*)Wvh,
                                                    KVDIM * DIM / 2);
    to_half<<<(DIM * DIM / 2 + 255) / 256, 256>>>((const float2*)Wo, (__half2*)Woh,
                                                  DIM * DIM / 2);

    cudaFuncSetAttribute(gemm_h<true>, cudaFuncAttributeMaxDynamicSharedMemorySize,
                         HGEMM_SMEM);
    cudaFuncSetAttribute(gemm_h<false>, cudaFuncAttributeMaxDynamicSharedMemorySize,
                         HGEMM_SMEM);

    gemm_h<true><<<dim3(DIM / 128, M / 128), 256, HGEMM_SMEM>>>(Xh, Wqh, Qh, M, DIM, DIM);
    gemm_h<true><<<dim3(KVDIM / 128, M / 128), 256, HGEMM_SMEM>>>(Xh, Wkh, Kh, M, KVDIM, DIM);
    gemm_h<true><<<dim3(KVDIM / 128, M / 128), 256, HGEMM_SMEM>>>(Xh, Wvh, Vh, M, KVDIM, DIM);

    const float scale = 0.08838834764831845f;  // 1/sqrt(128)
    rope_half<<<(BATCH * SEQ * NH * 64) / 256, 256>>>(Qh, DIM, NH, scale);
    rope_half<<<(BATCH * SEQ * NKV * 64) / 256, 256>>>(Kh, KVDIM, NKV, 1.0f);

    cudaFuncSetAttribute(attn_h, cudaFuncAttributeMaxDynamicSharedMemorySize,
                         ATTN_SMEM);
    attn_h<<<dim3(SEQ / 128, NH, BATCH), 256, ATTN_SMEM>>>(Qh, Kh, Vh, AOh);

    gemm_h<false><<<dim3(DIM / 128, M / 128), 256, HGEMM_SMEM>>>(AOh, Woh, out, M, DIM, DIM);
}

// round 7
// speedup vs baseline: 7.4215x; 1.1796x over previous
#include <cuda_runtime.h>
#include <cuda_fp16.h>
#include <math.h>
#include <stdint.h>

#define BATCH 2
#define SEQ   2048
#define DIM   2048
#define KVDIM 512
#define NH    16
#define NKV   4
#define HD    128

// Scratch (__device__ globals: allocation-free rule)
__device__ __half g_Xh[BATCH * SEQ * DIM];
__device__ __half g_Wqh[DIM * DIM];
__device__ __half g_Wkh[KVDIM * DIM];
__device__ __half g_Wvh[KVDIM * DIM];
__device__ __half g_Woh[DIM * DIM];
__device__ __half g_Qh[BATCH * SEQ * DIM];
__device__ __half g_Kh[BATCH * SEQ * KVDIM];
__device__ __half g_Vh[BATCH * SEQ * KVDIM];
__device__ __half g_AOh[BATCH * SEQ * DIM];

__device__ __forceinline__ uint32_t h2u(__half2 h) {
    uint32_t u;
    memcpy(&u, &h, 4);
    return u;
}

__device__ __forceinline__ uint32_t smem_u32(const void* p) {
    return (uint32_t)__cvta_generic_to_shared(p);
}

__device__ __forceinline__ void mma16(float* d, const uint32_t* a, const uint32_t* b) {
    asm volatile(
        "mma.sync.aligned.m16n8k16.row.col.f32.f16.f16.f32 "
        "{%0,%1,%2,%3}, {%4,%5,%6,%7}, {%8,%9}, {%0,%1,%2,%3};"
        : "+f"(d[0]), "+f"(d[1]), "+f"(d[2]), "+f"(d[3])
        : "r"(a[0]), "r"(a[1]), "r"(a[2]), "r"(a[3]), "r"(b[0]), "r"(b[1]));
}

__device__ __forceinline__ void ldsm4(uint32_t* r, uint32_t saddr) {
    asm volatile(
        "ldmatrix.sync.aligned.m8n8.x4.shared.b16 {%0,%1,%2,%3}, [%4];"
        : "=r"(r[0]), "=r"(r[1]), "=r"(r[2]), "=r"(r[3]) : "r"(saddr));
}
__device__ __forceinline__ void ldsm4t(uint32_t* r, uint32_t saddr) {
    asm volatile(
        "ldmatrix.sync.aligned.m8n8.x4.trans.shared.b16 {%0,%1,%2,%3}, [%4];"
        : "=r"(r[0]), "=r"(r[1]), "=r"(r[2]), "=r"(r[3]) : "r"(saddr));
}

__device__ __forceinline__ void cp16(void* smem_dst, const void* gmem_src) {
    uint32_t sa = (uint32_t)__cvta_generic_to_shared(smem_dst);
    asm volatile("cp.async.cg.shared.global [%0], [%1], 16;\n" ::"r"(sa), "l"(gmem_src));
}
#define CP_COMMIT() asm volatile("cp.async.commit_group;\n" ::)
#define CP_WAIT(N) asm volatile("cp.async.wait_group %0;\n" ::"n"(N))

// ---------------------------------------------------------------------------
__global__ void to_half(const float2* __restrict__ src, __half2* __restrict__ dst,
                        int n2) {
    int i = blockIdx.x * blockDim.x + threadIdx.x;
    if (i < n2) {
        float2 v = src[i];
        dst[i] = __floats2half2_rn(v.x, v.y);
    }
}

// ---------------------------------------------------------------------------
// fp16 GEMM via ldmatrix: C[m][n] = sum_k A[m][k]*B[n][k].
// Block 128x128, 8 warps (2Mx4N), warp 64x32, BK=32h, 3-stage cp.async.
// smem rows: 32 halves + pad (b32 stride 20 = 80B rows, phase-conflict-free).
// blockIdx.z selects (B0,C0) vs (B1,C1) so K/V projections share one launch.
// ---------------------------------------------------------------------------
#define HSTR2 20
#define HSTAGES 3
#define HSTAGE_U32 (128 * HSTR2)
#define HGEMM_SMEM (HSTAGES * 2 * HSTAGE_U32 * 4)  // 61440 B

template <bool HALF_OUT>
__global__ __launch_bounds__(256) void gemm_h(const __half* __restrict__ A,
                                              const __half* __restrict__ B0,
                                              void* __restrict__ C0,
                                              const __half* __restrict__ B1,
                                              void* __restrict__ C1,
                                              int M, int N, int K) {
    extern __shared__ uint32_t smp[];
    const __half* B = (blockIdx.z == 0) ? B0 : B1;
    void* Cv = (blockIdx.z == 0) ? C0 : C1;

    const uint32_t smb = smem_u32(smp);
    const int tid = threadIdx.x;
    const int lane = tid & 31;
    const int warp = tid >> 5;
    const int wm = warp >> 2;
    const int wn = warp & 3;
    const int gr = lane >> 2, tc = lane & 3;
    const int mBase = blockIdx.y * 128, nBase = blockIdx.x * 128;

    // ldmatrix lane offsets
    const int mat = lane >> 3;
    const int arow = (lane & 7) + ((mat & 1) << 3);   // A: row uses mat bit0
    const int acol = (mat >> 1) << 3;                 //    col uses mat bit1 (halves)
    const int brow = (lane & 7) + ((mat >> 1) << 3);  // B: row uses mat bit1
    const int bcol = (mat & 1) << 3;                  //    col uses mat bit0

    float acc[4][4][4];
#pragma unroll
    for (int i = 0; i < 4; i++)
#pragma unroll
        for (int j = 0; j < 4; j++)
#pragma unroll
            for (int r = 0; r < 4; r++) acc[i][j][r] = 0.f;

    const int nK = K / 32;

#define GSTAGE(kt, s)                                                          \
    do {                                                                       \
        _Pragma("unroll") for (int i = 0; i < 2; i++) {                        \
            int c = tid + i * 256;                                             \
            int r = c >> 2, ch = c & 3;                                        \
            cp16(&smp[((s)*128 + r) * HSTR2 + ch * 4],                         \
                 A + (size_t)(mBase + r) * K + (kt)*32 + ch * 8);              \
            cp16(&smp[(HSTAGES * 128 + (s)*128 + r) * HSTR2 + ch * 4],         \
                 B + (size_t)(nBase + r) * K + (kt)*32 + ch * 8);              \
        }                                                                      \
    } while (0)

    GSTAGE(0, 0);
    CP_COMMIT();
    GSTAGE(1, 1);
    CP_COMMIT();

    for (int kt = 0; kt < nK; kt++) {
        CP_WAIT(1);
        __syncthreads();
        int nxt = kt + 2;
        if (nxt < nK) GSTAGE(nxt, nxt % HSTAGES);
        CP_COMMIT();

        const uint32_t Aoff = smb + (uint32_t)(kt % HSTAGES) * (HSTAGE_U32 * 4);
        const uint32_t Boff = Aoff + HSTAGES * (HSTAGE_U32 * 4);
#pragma unroll
        for (int ks = 0; ks < 2; ks++) {
            const int k0h = ks * 16;  // halves
            uint32_t af[4][4], bf0[4], bf1[4];
#pragma unroll
            for (int mt = 0; mt < 4; mt++)
                ldsm4(af[mt], Aoff + (wm * 64 + mt * 16 + arow) * 80 +
                                  (k0h + acol) * 2);
            ldsm4(bf0, Boff + (wn * 32 + brow) * 80 + (k0h + bcol) * 2);
            ldsm4(bf1, Boff + (wn * 32 + 16 + brow) * 80 + (k0h + bcol) * 2);
#pragma unroll
            for (int mt = 0; mt < 4; mt++) {
                mma16(acc[mt][0], af[mt], bf0 + 0);
                mma16(acc[mt][1], af[mt], bf0 + 2);
                mma16(acc[mt][2], af[mt], bf1 + 0);
                mma16(acc[mt][3], af[mt], bf1 + 2);
            }
        }
        __syncthreads();
    }
#undef GSTAGE

#pragma unroll
    for (int mt = 0; mt < 4; mt++) {
        int m0 = mBase + wm * 64 + mt * 16;
#pragma unroll
        for (int nt = 0; nt < 4; nt++) {
            int n0 = nBase + wn * 32 + nt * 8 + 2 * tc;
            if (HALF_OUT) {
                __half2* cp = (__half2*)((__half*)Cv + (size_t)(m0 + gr) * N + n0);
                __half2* cp2 = (__half2*)((__half*)Cv + (size_t)(m0 + gr + 8) * N + n0);
                *cp = __floats2half2_rn(acc[mt][nt][0], acc[mt][nt][1]);
                *cp2 = __floats2half2_rn(acc[mt][nt][2], acc[mt][nt][3]);
            } else {
                float* cp = (float*)Cv + (size_t)(m0 + gr) * N + n0;
                float* cp2 = (float*)Cv + (size_t)(m0 + gr + 8) * N + n0;
                cp[0] = acc[mt][nt][0];
                cp[1] = acc[mt][nt][1];
                cp2[0] = acc[mt][nt][2];
                cp2[1] = acc[mt][nt][3];
            }
        }
    }
}

// ---------------------------------------------------------------------------
// RoPE in-place on half (+scale)
// ---------------------------------------------------------------------------
__global__ void rope_half(__half* __restrict__ X, int nCols, int nHeads,
                          float scale) {
    int idx = blockIdx.x * blockDim.x + threadIdx.x;
    int i = idx & 63;
    int h = (idx >> 6) % nHeads;
    int row = idx / (64 * nHeads);
    int l = row & (SEQ - 1);

    float freq = expf(-(float)i * 0.14391156831212787f);
    float ang = (float)l * freq;
    float s, c;
    sincosf(ang, &s, &c);

    __half* p = X + (size_t)row * nCols + h * HD + i;
    float x1 = __half2float(p[0]);
    float x2 = __half2float(p[64]);
    p[0] = __float2half_rn((x1 * c - x2 * s) * scale);
    p[64] = __float2half_rn((x2 * c + x1 * s) * scale);
}

// ---------------------------------------------------------------------------
// Flash attention, fp16 mma + ldmatrix, cp.async pipelined.
// CTA: 256 thr (8 warps x 16 q-rows = 128 q), KV tiles of 64.
// smem (b32 strides): Qs[128][68], Ks[2][64][68], Vs[64][68], Ps[128][36]
// ---------------------------------------------------------------------------
#define AQS2 68
#define APS2 36
#define ATTN_SMEM ((128 * AQS2 + 2 * 64 * AQS2 + 64 * AQS2 + 128 * APS2) * 4)

__global__ __launch_bounds__(256) void attn_h(const __half* __restrict__ Q,
                                              const __half* __restrict__ K,
                                              const __half* __restrict__ V,
                                              __half* __restrict__ O) {
    extern __shared__ uint32_t sm[];
    uint32_t* Qs = sm;                       // [128][68] b32
    uint32_t* Ks = Qs + 128 * AQS2;          // [2][64][68]
    uint32_t* Vs = Ks + 2 * 64 * AQS2;       // [64][68]
    uint32_t* Ps = Vs + 64 * AQS2;           // [128][36]

    const uint32_t Qaddr = smem_u32(Qs);
    const uint32_t Kaddr0 = smem_u32(Ks);
    const uint32_t Vaddr = smem_u32(Vs);
    const uint32_t Paddr = smem_u32(Ps);

    const int tid = threadIdx.x, lane = tid & 31, warp = tid >> 5;
    const int gr = lane >> 2, tc = lane & 3;
    const int qTile = blockIdx.x, h = blockIdx.y, b = blockIdx.z;
    const int kh = h >> 2;
    const int qBase = qTile * 128;

    // ldmatrix lane offsets (bytes computed at use)
    const int mat = lane >> 3;
    const int arow = (lane & 7) + ((mat & 1) << 3);   // A-layout / V-trans rows
    const int acol = (mat >> 1) << 3;                 // halves
    const int brow = (lane & 7) + ((mat >> 1) << 3);  // B(K)-layout rows
    const int bcol = (mat & 1) << 3;

    const __half* Qp = Q + ((size_t)(b * SEQ + qBase)) * DIM + h * HD;
    const __half* Kbase = K + ((size_t)(b * SEQ)) * KVDIM + kh * HD;
    const __half* Vbase = V + ((size_t)(b * SEQ)) * KVDIM + kh * HD;

    // Prologue: stage Q + K(0)
    {
#pragma unroll
        for (int i = 0; i < 8; i++) {
            int c = tid + i * 256;
            int q = c >> 4;
            int ch = c & 15;
            cp16((char*)Qs + q * (AQS2 * 4) + ch * 16, Qp + (size_t)q * DIM + ch * 8);
        }
#pragma unroll
        for (int i = 0; i < 4; i++) {
            int c = tid + i * 256;
            int key = c >> 4;
            int ch = c & 15;
            cp16((char*)Ks + key * (AQS2 * 4) + ch * 16,
                 Kbase + (size_t)key * KVDIM + ch * 8);
        }
        CP_COMMIT();
    }

    float m0r = -1e30f, m1r = -1e30f, l0 = 0.f, l1 = 0.f;
    float o[16][4];
#pragma unroll
    for (int i = 0; i < 16; i++)
#pragma unroll
        for (int j = 0; j < 4; j++) o[i][j] = 0.f;

    const int q0 = warp * 16;
    const int nT = 2 * qTile + 2;

    for (int t = 0; t < nT; t++) {
        const int buf = t & 1;
        CP_WAIT(0);
        __syncthreads();

        // Issue V(t)
        {
            const __half* Vp = Vbase + (size_t)(t * 64) * KVDIM;
#pragma unroll
            for (int i = 0; i < 4; i++) {
                int c = tid + i * 256;
                int key = c >> 4;
                int ch = c & 15;
                cp16((char*)Vs + key * (AQS2 * 4) + ch * 16,
                     Vp + (size_t)key * KVDIM + ch * 8);
            }
        }
        CP_COMMIT();
        // Issue K(t+1)
        if (t + 1 < nT) {
            const __half* Kp = Kbase + (size_t)((t + 1) * 64) * KVDIM;
            uint32_t* Kd = Ks + ((t + 1) & 1) * 64 * AQS2;
#pragma unroll
            for (int i = 0; i < 4; i++) {
                int c = tid + i * 256;
                int key = c >> 4;
                int ch = c & 15;
                cp16((char*)Kd + key * (AQS2 * 4) + ch * 16,
                     Kp + (size_t)key * KVDIM + ch * 8);
            }
        }
        CP_COMMIT();

        // S = Q * K^T (16 q x 64 keys per warp); ldmatrix frags
        const uint32_t Kaddr = Kaddr0 + (uint32_t)buf * (64 * AQS2 * 4);
        float s[8][4];
#pragma unroll
        for (int nt = 0; nt < 8; nt++)
#pragma unroll
            for (int r = 0; r < 4; r++) s[nt][r] = 0.f;

#pragma unroll
        for (int dk = 0; dk < 8; dk++) {
            const int d0h = dk * 16;
            uint32_t aq[4];
            ldsm4(aq, Qaddr + (q0 + arow) * (AQS2 * 4) + (d0h + acol) * 2);
#pragma unroll
            for (int p = 0; p < 4; p++) {
                uint32_t bk[4];
                ldsm4(bk, Kaddr + (p * 16 + brow) * (AQS2 * 4) + (d0h + bcol) * 2);
                mma16(s[2 * p], aq, bk + 0);
                mma16(s[2 * p + 1], aq, bk + 2);
            }
        }

        // Causal mask
        if (t * 64 >= qBase) {
            int qrow = qBase + q0 + gr;
            int kcol = t * 64 + 2 * tc;
#pragma unroll
            for (int nt = 0; nt < 8; nt++) {
                int kc = kcol + nt * 8;
                if (kc > qrow) s[nt][0] = -1e30f;
                if (kc + 1 > qrow) s[nt][1] = -1e30f;
                if (kc > qrow + 8) s[nt][2] = -1e30f;
                if (kc + 1 > qrow + 8) s[nt][3] = -1e30f;
            }
        }

        // Online softmax
        float rm0 = -1e30f, rm1 = -1e30f;
#pragma unroll
        for (int nt = 0; nt < 8; nt++) {
            rm0 = fmaxf(rm0, fmaxf(s[nt][0], s[nt][1]));
            rm1 = fmaxf(rm1, fmaxf(s[nt][2], s[nt][3]));
        }
        rm0 = fmaxf(rm0, __shfl_xor_sync(0xffffffffu, rm0, 1));
        rm0 = fmaxf(rm0, __shfl_xor_sync(0xffffffffu, rm0, 2));
        rm1 = fmaxf(rm1, __shfl_xor_sync(0xffffffffu, rm1, 1));
        rm1 = fmaxf(rm1, __shfl_xor_sync(0xffffffffu, rm1, 2));

        float mn0 = fmaxf(m0r, rm0), mn1 = fmaxf(m1r, rm1);
        float a0 = __expf(m0r - mn0), a1 = __expf(m1r - mn1);
        m0r = mn0;
        m1r = mn1;

        float rs0 = 0.f, rs1 = 0.f;
#pragma unroll
        for (int nt = 0; nt < 8; nt++) {
            s[nt][0] = __expf(s[nt][0] - mn0);
            s[nt][1] = __expf(s[nt][1] - mn0);
            s[nt][2] = __expf(s[nt][2] - mn1);
            s[nt][3] = __expf(s[nt][3] - mn1);
            rs0 += s[nt][0] + s[nt][1];
            rs1 += s[nt][2] + s[nt][3];
        }
        rs0 += __shfl_xor_sync(0xffffffffu, rs0, 1);
        rs0 += __shfl_xor_sync(0xffffffffu, rs0, 2);
        rs1 += __shfl_xor_sync(0xffffffffu, rs1, 1);
        rs1 += __shfl_xor_sync(0xffffffffu, rs1, 2);
        l0 = l0 * a0 + rs0;
        l1 = l1 * a1 + rs1;

#pragma unroll
        for (int ot = 0; ot < 16; ot++) {
            o[ot][0] *= a0;
            o[ot][1] *= a0;
            o[ot][2] *= a1;
            o[ot][3] *= a1;
        }

        // V(t) must have landed
        CP_WAIT(1);
        __syncthreads();

        // P -> smem (half2, warp-private rows)
#pragma unroll
        for (int nt = 0; nt < 8; nt++) {
            Ps[(q0 + gr) * APS2 + nt * 4 + tc] =
                h2u(__floats2half2_rn(s[nt][0], s[nt][1]));
            Ps[(q0 + gr + 8) * APS2 + nt * 4 + tc] =
                h2u(__floats2half2_rn(s[nt][2], s[nt][3]));
        }
        __syncwarp();

        // O += P * V : P frags via ldmatrix, V frags via ldmatrix.trans
#pragma unroll
        for (int kk = 0; kk < 4; kk++) {
            const int k0h = kk * 16;
            uint32_t ap[4];
            ldsm4(ap, Paddr + (q0 + arow) * (APS2 * 4) + (k0h + acol) * 2);
#pragma unroll
            for (int dp = 0; dp < 8; dp++) {
                uint32_t bv[4];
                ldsm4t(bv, Vaddr + (k0h + arow) * (AQS2 * 4) + (dp * 16 + acol) * 2);
                mma16(o[2 * dp], ap, bv + 0);
                mma16(o[2 * dp + 1], ap, bv + 2);
            }
        }
        __syncwarp();
    }

    // Normalize + write half (feeds O-projection GEMM)
    float inv0 = 1.f / l0, inv1 = 1.f / l1;
    __half* Op = O + ((size_t)(b * SEQ + qBase + q0)) * DIM + h * HD;
#pragma unroll
    for (int ot = 0; ot < 16; ot++) {
        int d0 = ot * 8 + 2 * tc;
        *(__half2*)(Op + (size_t)gr * DIM + d0) =
            __floats2half2_rn(o[ot][0] * inv0, o[ot][1] * inv0);
        *(__half2*)(Op + (size_t)(gr + 8) * DIM + d0) =
            __floats2half2_rn(o[ot][2] * inv1, o[ot][3] * inv1);
    }
}

// ---------------------------------------------------------------------------
extern "C" void kernel_launch(void* const* d_in, const int* in_sizes, int n_in,
                              void* d_out, int out_size) {
    const float* x = (const float*)d_in[0];
    const float* Wq = (const float*)d_in[1];
    const float* Wk = (const float*)d_in[2];
    const float* Wv = (const float*)d_in[3];
    const float* Wo = (const float*)d_in[4];
    float* out = (float*)d_out;

    __half *Xh, *Wqh, *Wkh, *Wvh, *Woh, *Qh, *Kh, *Vh, *AOh;
    cudaGetSymbolAddress((void**)&Xh, g_Xh);
    cudaGetSymbolAddress((void**)&Wqh, g_Wqh);
    cudaGetSymbolAddress((void**)&Wkh, g_Wkh);
    cudaGetSymbolAddress((void**)&Wvh, g_Wvh);
    cudaGetSymbolAddress((void**)&Woh, g_Woh);
    cudaGetSymbolAddress((void**)&Qh, g_Qh);
    cudaGetSymbolAddress((void**)&Kh, g_Kh);
    cudaGetSymbolAddress((void**)&Vh, g_Vh);
    cudaGetSymbolAddress((void**)&AOh, g_AOh);

    const int M = BATCH * SEQ;  // 4096

    to_half<<<(M * DIM / 2 + 255) / 256, 256>>>((const float2*)x, (__half2*)Xh,
                                                M * DIM / 2);
    to_half<<<(DIM * DIM / 2 + 255) / 256, 256>>>((const float2*)Wq, (__half2*)Wqh,
                                                  DIM * DIM / 2);
    to_half<<<(KVDIM * DIM / 2 + 255) / 256, 256>>>((const float2*)Wk, (__half2*)Wkh,
                                                    KVDIM * DIM / 2);
    to_half<<<(KVDIM * DIM / 2 + 255) / 256, 256>>>((const float2*)Wv, (__half2*)Wvh,
                                                    KVDIM * DIM / 2);
    to_half<<<(DIM * DIM / 2 + 255) / 256, 256>>>((const float2*)Wo, (__half2*)Woh,
                                                  DIM * DIM / 2);

    cudaFuncSetAttribute(gemm_h<true>, cudaFuncAttributeMaxDynamicSharedMemorySize,
                         HGEMM_SMEM);
    cudaFuncSetAttribute(gemm_h<false>, cudaFuncAttributeMaxDynamicSharedMemorySize,
                         HGEMM_SMEM);

    // Q projection
    gemm_h<true><<<dim3(DIM / 128, M / 128, 1), 256, HGEMM_SMEM>>>(
        Xh, Wqh, Qh, Wqh, Qh, M, DIM, DIM);
    // K and V projections in one launch (z selects)
    gemm_h<true><<<dim3(KVDIM / 128, M / 128, 2), 256, HGEMM_SMEM>>>(
        Xh, Wkh, Kh, Wvh, Vh, M, KVDIM, DIM);

    const float scale = 0.08838834764831845f;  // 1/sqrt(128)
    rope_half<<<(BATCH * SEQ * NH * 64) / 256, 256>>>(Qh, DIM, NH, scale);
    rope_half<<<(BATCH * SEQ * NKV * 64) / 256, 256>>>(Kh, KVDIM, NKV, 1.0f);

    cudaFuncSetAttribute(attn_h, cudaFuncAttributeMaxDynamicSharedMemorySize,
                         ATTN_SMEM);
    attn_h<<<dim3(SEQ / 128, NH, BATCH), 256, ATTN_SMEM>>>(Qh, Kh, Vh, AOh);

    gemm_h<false><<<dim3(DIM / 128, M / 128, 1), 256, HGEMM_SMEM>>>(
        AOh, Woh, out, Woh, out, M, DIM, DIM);
}